// round 1
// baseline (speedup 1.0000x reference)
#include <cuda_runtime.h>
#include <cstdint>

// Problem constants (fixed by the dataset)
constexpr int B_    = 8;
constexpr int C_    = 1024;
constexpr int T_IN  = 8192;
constexpr int POOLK = 4;
constexpr int T_    = T_IN / POOLK;   // 2048
constexpr int MAXL  = 16;
constexpr long NELEM = (long)B_ * C_ * T_;  // 16,777,216

// d_out layout: [ret | tap | ff1 | ff2], each NELEM floats.

// ---------------------------------------------------------------------------
// Kernel 1: 4:1 mean pool along T.  tap[i] = mean(x[4i..4i+3])
// ---------------------------------------------------------------------------
__global__ void pool_kernel(const float* __restrict__ x, float* __restrict__ tap)
{
    long i = (long)blockIdx.x * blockDim.x + threadIdx.x;
    if (i >= NELEM) return;
    float4 v = reinterpret_cast<const float4*>(x)[i];
    tap[i] = 0.25f * (v.x + v.y + v.z + v.w);
}

// ---------------------------------------------------------------------------
// Kernel 2: batched SGEMM with bias.
//   C[b][m][n] = sum_k A[m][k] * Bm[b][k][n] + bias[m]
//   A: 1024x1024 row-major (W), Bm: per-batch 1024x2048, C: per-batch 1024x2048
// Tile: BM=BN=128, BK=8, 256 threads, 8x8 micro-tile per thread.
// ---------------------------------------------------------------------------
#define BM 128
#define BN 128
#define BK 8

__global__ __launch_bounds__(256, 2)
void sgemm_bias_kernel(const float* __restrict__ A,
                       const float* __restrict__ Bmat,
                       const float* __restrict__ bias,
                       float* __restrict__ Cmat)
{
    const int M = C_;       // 1024
    const int N = T_;       // 2048
    const int K = C_;       // 1024

    __shared__ float As[BK][BM];
    __shared__ float Bs[BK][BN];

    const int bn = blockIdx.x * BN;
    const int bm = blockIdx.y * BM;
    const size_t batch_off = (size_t)blockIdx.z * (size_t)K * (size_t)N;
    const float* Bb = Bmat + batch_off;
    float*       Cb = Cmat + batch_off;

    const int tid = threadIdx.x;

    // A-tile load mapping: 128 rows x 8 cols, float4 per thread
    const int ar  = tid >> 1;            // 0..127
    const int ac4 = (tid & 1) * 4;       // 0 or 4
    // B-tile load mapping: 8 rows x 128 cols, float4 per thread
    const int br  = tid >> 5;            // 0..7
    const int bc4 = (tid & 31) * 4;      // 0..124

    // Compute mapping: 16x16 thread grid, each 8x8 outputs
    const int ty = tid >> 4;             // 0..15
    const int tx = tid & 15;             // 0..15
    const int row0 = ty * 8;
    const int col0 = tx * 8;

    float acc[8][8];
    #pragma unroll
    for (int i = 0; i < 8; i++)
        #pragma unroll
        for (int j = 0; j < 8; j++)
            acc[i][j] = 0.0f;

    const float* Aptr = A + (size_t)(bm + ar) * K + ac4;
    const float* Bptr = Bb + (size_t)br * N + bn + bc4;

    for (int k0 = 0; k0 < K; k0 += BK) {
        // Load A tile (transpose into As[k][m])
        float4 av = *reinterpret_cast<const float4*>(Aptr + k0);
        As[ac4 + 0][ar] = av.x;
        As[ac4 + 1][ar] = av.y;
        As[ac4 + 2][ar] = av.z;
        As[ac4 + 3][ar] = av.w;
        // Load B tile (direct)
        float4 bv = *reinterpret_cast<const float4*>(Bptr + (size_t)k0 * N);
        *reinterpret_cast<float4*>(&Bs[br][bc4]) = bv;

        __syncthreads();

        #pragma unroll
        for (int kk = 0; kk < BK; kk++) {
            float a[8], b[8];
            float4 a0 = *reinterpret_cast<const float4*>(&As[kk][row0]);
            float4 a1 = *reinterpret_cast<const float4*>(&As[kk][row0 + 4]);
            float4 b0 = *reinterpret_cast<const float4*>(&Bs[kk][col0]);
            float4 b1 = *reinterpret_cast<const float4*>(&Bs[kk][col0 + 4]);
            a[0]=a0.x; a[1]=a0.y; a[2]=a0.z; a[3]=a0.w;
            a[4]=a1.x; a[5]=a1.y; a[6]=a1.z; a[7]=a1.w;
            b[0]=b0.x; b[1]=b0.y; b[2]=b0.z; b[3]=b0.w;
            b[4]=b1.x; b[5]=b1.y; b[6]=b1.z; b[7]=b1.w;
            #pragma unroll
            for (int i = 0; i < 8; i++)
                #pragma unroll
                for (int j = 0; j < 8; j++)
                    acc[i][j] = fmaf(a[i], b[j], acc[i][j]);
        }

        __syncthreads();
    }

    // Epilogue: add bias and store
    #pragma unroll
    for (int i = 0; i < 8; i++) {
        const float bvv = bias[bm + row0 + i];
        float* crow = Cb + (size_t)(bm + row0 + i) * N + bn + col0;
        float4 o0 = make_float4(acc[i][0] + bvv, acc[i][1] + bvv,
                                acc[i][2] + bvv, acc[i][3] + bvv);
        float4 o1 = make_float4(acc[i][4] + bvv, acc[i][5] + bvv,
                                acc[i][6] + bvv, acc[i][7] + bvv);
        reinterpret_cast<float4*>(crow)[0] = o0;
        reinterpret_cast<float4*>(crow + 4)[0] = o1;
    }
}

// ---------------------------------------------------------------------------
// Kernel 3: causal windowed mean (L = min(s+1, 16)) sampled at s = 4*g,
// broadcast to 4 consecutive output positions.
//   ret[row][4g .. 4g+3] = mean(ff2[row][s-L+1 .. s]),  s = 4g
// ---------------------------------------------------------------------------
__global__ void window_kernel(const float* __restrict__ ff2, float* __restrict__ ret)
{
    const long total = (long)B_ * C_ * (T_ / 4);
    long i = (long)blockIdx.x * blockDim.x + threadIdx.x;
    if (i >= total) return;

    const int g   = (int)(i % (T_ / 4));
    const long row = i / (T_ / 4);
    const int s = g * 4;
    const int L = (s + 1 < MAXL) ? (s + 1) : MAXL;

    const float* p = ff2 + row * (long)T_;
    float sum = 0.0f;
    #pragma unroll 4
    for (int j = s - L + 1; j <= s; j++)
        sum += p[j];
    const float avg = sum / (float)L;

    float4 o = make_float4(avg, avg, avg, avg);
    reinterpret_cast<float4*>(ret + row * (long)T_)[g] = o;
}

// ---------------------------------------------------------------------------
// Launcher
// ---------------------------------------------------------------------------
extern "C" void kernel_launch(void* const* d_in, const int* in_sizes, int n_in,
                              void* d_out, int out_size)
{
    const float* x  = (const float*)d_in[0];
    const float* W1 = (const float*)d_in[1];
    const float* b1 = (const float*)d_in[2];
    const float* W2 = (const float*)d_in[3];
    const float* b2 = (const float*)d_in[4];

    float* out = (float*)d_out;
    float* ret = out;                 // [B,C,T]
    float* tap = out + NELEM;         // [B,C,T]
    float* ff1 = out + 2 * NELEM;     // [B,C,T]
    float* ff2 = out + 3 * NELEM;     // [B,C,T]

    // 1. pool
    {
        const int thr = 256;
        const long n = NELEM;
        const int blocks = (int)((n + thr - 1) / thr);
        pool_kernel<<<blocks, thr>>>(x, tap);
    }

    // 2. ff1 = W1 @ tap + b1
    {
        dim3 grid(T_ / BN, C_ / BM, B_);
        sgemm_bias_kernel<<<grid, 256>>>(W1, tap, b1, ff1);
    }

    // 3. ff2 = W2 @ ff1 + b2
    {
        dim3 grid(T_ / BN, C_ / BM, B_);
        sgemm_bias_kernel<<<grid, 256>>>(W2, ff1, b2, ff2);
    }

    // 4. windowed mean + stride-4 gather -> ret
    {
        const int thr = 256;
        const long n = (long)B_ * C_ * (T_ / 4);
        const int blocks = (int)((n + thr - 1) / thr);
        window_kernel<<<blocks, thr>>>(ff2, ret);
    }
}

// round 3
// speedup vs baseline: 2.5814x; 2.5814x over previous
#include <cuda_runtime.h>
#include <cuda_bf16.h>
#include <cstdint>

// ---------------------------------------------------------------------------
// Problem constants
// ---------------------------------------------------------------------------
constexpr int B_ = 8;
constexpr int C_ = 1024;     // M and K of both GEMMs
constexpr int T_ = 2048;     // N of both GEMMs
constexpr long NELEM = (long)B_ * C_ * T_;   // 16,777,216

// d_out layout: [ret | tap | ff1 | ff2], each NELEM floats.

// ---------------------------------------------------------------------------
// helpers
// ---------------------------------------------------------------------------
__device__ __forceinline__ uint32_t smem_u32(const void* p) {
    uint32_t a;
    asm("{ .reg .u64 t; cvta.to.shared.u64 t, %1; cvt.u32.u64 %0, t; }"
        : "=r"(a) : "l"(p));
    return a;
}

__device__ __forceinline__ void ldsm_x4(uint32_t (&r)[4], uint32_t addr) {
    asm volatile("ldmatrix.sync.aligned.m8n8.x4.shared.b16 {%0,%1,%2,%3}, [%4];"
        : "=r"(r[0]), "=r"(r[1]), "=r"(r[2]), "=r"(r[3]) : "r"(addr));
}
__device__ __forceinline__ void ldsm_x2t(uint32_t (&r)[2], uint32_t addr) {
    asm volatile("ldmatrix.sync.aligned.m8n8.x2.trans.shared.b16 {%0,%1}, [%2];"
        : "=r"(r[0]), "=r"(r[1]) : "r"(addr));
}
__device__ __forceinline__ void mma_bf16(float (&d)[4],
                                         const uint32_t (&a)[4],
                                         const uint32_t (&b)[2]) {
    asm volatile(
        "mma.sync.aligned.m16n8k16.row.col.f32.bf16.bf16.f32 "
        "{%0,%1,%2,%3}, {%4,%5,%6,%7}, {%8,%9}, {%0,%1,%2,%3};"
        : "+f"(d[0]), "+f"(d[1]), "+f"(d[2]), "+f"(d[3])
        : "r"(a[0]), "r"(a[1]), "r"(a[2]), "r"(a[3]), "r"(b[0]), "r"(b[1]));
}

__device__ __forceinline__ uint32_t pack_bf16x2(__nv_bfloat16 a, __nv_bfloat16 b) {
    __nv_bfloat162 p; p.x = a; p.y = b;
    return *reinterpret_cast<uint32_t*>(&p);
}

// ---------------------------------------------------------------------------
// Kernel 1: 4:1 mean pool.  tap[i] = mean(x[4i..4i+3])
// ---------------------------------------------------------------------------
__global__ void pool_kernel(const float* __restrict__ x, float* __restrict__ tap)
{
    long i = (long)blockIdx.x * blockDim.x + threadIdx.x;
    if (i >= NELEM) return;
    float4 v = reinterpret_cast<const float4*>(x)[i];
    tap[i] = 0.25f * (v.x + v.y + v.z + v.w);
}

// ---------------------------------------------------------------------------
// Kernel 2: HMMA GEMM with in-kernel bf16 3-term split.
//   out[b][m][n] = sum_k W[m][k] * X[b][k][n] + bias[m]
// CTA tile 128x128, K-chunk 32, 256 threads (8 warps, warp tile 64x32),
// double-buffered SMEM with padded rows for conflict-free ldmatrix.
// ---------------------------------------------------------------------------
constexpr int KC = 32;
constexpr int A_STR = 40;    // bf16 elems per A row (32 + 8 pad) -> 80 B
constexpr int B_STR = 136;   // bf16 elems per B row (128 + 8 pad) -> 272 B
constexpr int A_BYTES = 128 * A_STR * 2;   // 10240
constexpr int B_BYTES = KC * B_STR * 2;    // 8704
constexpr int BUF_BYTES = 2 * A_BYTES + 2 * B_BYTES;   // 37888
constexpr int GEMM_SMEM = 2 * BUF_BYTES;               // 75776
// per-buffer offsets
constexpr int OF_AHI = 0;
constexpr int OF_ALO = A_BYTES;
constexpr int OF_BHI = 2 * A_BYTES;
constexpr int OF_BLO = 2 * A_BYTES + B_BYTES;

__global__ __launch_bounds__(256, 1)
void gemm_mma_kernel(const float* __restrict__ A,     // W [1024,1024]
                     const float* __restrict__ X,     // [B,1024,2048]
                     const float* __restrict__ bias,
                     float* __restrict__ out)         // [B,1024,2048]
{
    extern __shared__ char smem[];
    const uint32_t sb = smem_u32(smem);

    const int tid  = threadIdx.x;
    const int wid  = tid >> 5;
    const int lane = tid & 31;
    const int bn = blockIdx.x * 128;
    const int bm = blockIdx.y * 128;
    const int bz = blockIdx.z;

    // warp tiling: 2 (M) x 4 (N)
    const int wm = (wid & 1) * 64;    // warp row offset
    const int wn = (wid >> 1) * 32;   // warp col offset

    const float* Xb = X + (size_t)bz * C_ * T_;

    float acc[4][4][4];
    #pragma unroll
    for (int i = 0; i < 4; i++)
        #pragma unroll
        for (int j = 0; j < 4; j++)
            #pragma unroll
            for (int k = 0; k < 4; k++)
                acc[i][j][k] = 0.0f;

    // ---- global load / smem store lane mappings ----
    // A: 128 rows x 32 floats = 1024 float4; 4 per thread
    const int a_r  = tid >> 1;              // row pair base: idx4 = tid + i*256 -> r = idx4>>3
    // (recomputed in loop from idx4 for clarity)
    // ldmatrix lane bases
    const int lA_row = (lane & 15);
    const int lA_k   = (lane >> 4) << 3;    // 0 or 8
    const int lB_row = (lane & 15);

    // per-term smem bases (buffer added in loop)
    const uint32_t aHiBase = sb + OF_AHI;
    const uint32_t aLoBase = sb + OF_ALO;
    const uint32_t bHiBase = sb + OF_BHI;
    const uint32_t bLoBase = sb + OF_BLO;

    float4 ra[4], rb[4];

    // ---- prologue: load chunk 0 and store to buffer 0 ----
    #pragma unroll
    for (int i = 0; i < 4; i++) {
        int idx4 = tid + i * 256;
        int r = idx4 >> 3, c = (idx4 & 7) * 4;
        ra[i] = *reinterpret_cast<const float4*>(A + (size_t)(bm + r) * C_ + c);
        int rbr = idx4 >> 5, rbc = (idx4 & 31) * 4;
        rb[i] = *reinterpret_cast<const float4*>(Xb + (size_t)rbr * T_ + bn + rbc);
    }
    {
        #pragma unroll
        for (int i = 0; i < 4; i++) {
            int idx4 = tid + i * 256;
            int r = idx4 >> 3, c = (idx4 & 7) * 4;
            float v[4] = {ra[i].x, ra[i].y, ra[i].z, ra[i].w};
            __nv_bfloat16 h[4], l[4];
            #pragma unroll
            for (int q = 0; q < 4; q++) {
                h[q] = __float2bfloat16(v[q]);
                l[q] = __float2bfloat16(v[q] - __bfloat162float(h[q]));
            }
            uint2 uh = make_uint2(pack_bf16x2(h[0], h[1]), pack_bf16x2(h[2], h[3]));
            uint2 ul = make_uint2(pack_bf16x2(l[0], l[1]), pack_bf16x2(l[2], l[3]));
            *reinterpret_cast<uint2*>(smem + OF_AHI + (r * A_STR + c) * 2) = uh;
            *reinterpret_cast<uint2*>(smem + OF_ALO + (r * A_STR + c) * 2) = ul;

            int br = idx4 >> 5, bc = (idx4 & 31) * 4;
            float w[4] = {rb[i].x, rb[i].y, rb[i].z, rb[i].w};
            #pragma unroll
            for (int q = 0; q < 4; q++) {
                h[q] = __float2bfloat16(w[q]);
                l[q] = __float2bfloat16(w[q] - __bfloat162float(h[q]));
            }
            uh = make_uint2(pack_bf16x2(h[0], h[1]), pack_bf16x2(h[2], h[3]));
            ul = make_uint2(pack_bf16x2(l[0], l[1]), pack_bf16x2(l[2], l[3]));
            *reinterpret_cast<uint2*>(smem + OF_BHI + (br * B_STR + bc) * 2) = uh;
            *reinterpret_cast<uint2*>(smem + OF_BLO + (br * B_STR + bc) * 2) = ul;
        }
    }
    __syncthreads();

    // ---- mainloop over 32 K-chunks ----
    for (int ch = 0; ch < C_ / KC; ch++) {
        const int buf = ch & 1;
        const uint32_t bufOff = buf * BUF_BYTES;

        // prefetch next chunk
        if (ch + 1 < C_ / KC) {
            const int k0 = (ch + 1) * KC;
            #pragma unroll
            for (int i = 0; i < 4; i++) {
                int idx4 = tid + i * 256;
                int r = idx4 >> 3, c = (idx4 & 7) * 4;
                ra[i] = *reinterpret_cast<const float4*>(A + (size_t)(bm + r) * C_ + k0 + c);
                int br = idx4 >> 5, bc = (idx4 & 31) * 4;
                rb[i] = *reinterpret_cast<const float4*>(Xb + (size_t)(k0 + br) * T_ + bn + bc);
            }
        }

        // compute 2 k16 steps from current buffer
        #pragma unroll
        for (int ks = 0; ks < 2; ks++) {
            uint32_t ahi[4][4], alo[4][4];
            uint32_t bhi[4][2], blo[4][2];
            #pragma unroll
            for (int mb = 0; mb < 4; mb++) {
                int row = wm + mb * 16 + lA_row;
                int kel = ks * 16 + lA_k;
                uint32_t off = bufOff + (uint32_t)(row * A_STR + kel) * 2;
                ldsm_x4(ahi[mb], aHiBase + off);
                ldsm_x4(alo[mb], aLoBase + off);
            }
            #pragma unroll
            for (int nb = 0; nb < 4; nb++) {
                int krow = ks * 16 + lB_row;
                int ncol = wn + nb * 8;
                uint32_t off = bufOff + (uint32_t)(krow * B_STR + ncol) * 2;
                ldsm_x2t(bhi[nb], bHiBase + off);
                ldsm_x2t(blo[nb], bLoBase + off);
            }
            #pragma unroll
            for (int mb = 0; mb < 4; mb++) {
                #pragma unroll
                for (int nb = 0; nb < 4; nb++) {
                    mma_bf16(acc[mb][nb], ahi[mb], bhi[nb]);
                    mma_bf16(acc[mb][nb], ahi[mb], blo[nb]);
                    mma_bf16(acc[mb][nb], alo[mb], bhi[nb]);
                }
            }
        }

        // store prefetched chunk into other buffer
        if (ch + 1 < C_ / KC) {
            const uint32_t nb_ = (buf ^ 1) * BUF_BYTES;
            #pragma unroll
            for (int i = 0; i < 4; i++) {
                int idx4 = tid + i * 256;
                int r = idx4 >> 3, c = (idx4 & 7) * 4;
                float v[4] = {ra[i].x, ra[i].y, ra[i].z, ra[i].w};
                __nv_bfloat16 h[4], l[4];
                #pragma unroll
                for (int q = 0; q < 4; q++) {
                    h[q] = __float2bfloat16(v[q]);
                    l[q] = __float2bfloat16(v[q] - __bfloat162float(h[q]));
                }
                uint2 uh = make_uint2(pack_bf16x2(h[0], h[1]), pack_bf16x2(h[2], h[3]));
                uint2 ul = make_uint2(pack_bf16x2(l[0], l[1]), pack_bf16x2(l[2], l[3]));
                *reinterpret_cast<uint2*>(smem + nb_ + OF_AHI + (r * A_STR + c) * 2) = uh;
                *reinterpret_cast<uint2*>(smem + nb_ + OF_ALO + (r * A_STR + c) * 2) = ul;

                int br = idx4 >> 5, bc = (idx4 & 31) * 4;
                float w[4] = {rb[i].x, rb[i].y, rb[i].z, rb[i].w};
                #pragma unroll
                for (int q = 0; q < 4; q++) {
                    h[q] = __float2bfloat16(w[q]);
                    l[q] = __float2bfloat16(w[q] - __bfloat162float(h[q]));
                }
                uh = make_uint2(pack_bf16x2(h[0], h[1]), pack_bf16x2(h[2], h[3]));
                ul = make_uint2(pack_bf16x2(l[0], l[1]), pack_bf16x2(l[2], l[3]));
                *reinterpret_cast<uint2*>(smem + nb_ + OF_BHI + (br * B_STR + bc) * 2) = uh;
                *reinterpret_cast<uint2*>(smem + nb_ + OF_BLO + (br * B_STR + bc) * 2) = ul;
            }
        }
        __syncthreads();
    }

    // ---- epilogue: bias + store ----
    const int r_lo = lane >> 2;           // 0..7
    const int c_lo = (lane & 3) * 2;      // 0,2,4,6
    #pragma unroll
    for (int mb = 0; mb < 4; mb++) {
        int gr0 = bm + wm + mb * 16 + r_lo;
        int gr1 = gr0 + 8;
        float bv0 = bias[gr0];
        float bv1 = bias[gr1];
        float* o0 = out + ((size_t)bz * C_ + gr0) * T_ + bn + wn + c_lo;
        float* o1 = out + ((size_t)bz * C_ + gr1) * T_ + bn + wn + c_lo;
        #pragma unroll
        for (int nb = 0; nb < 4; nb++) {
            float2 v0 = make_float2(acc[mb][nb][0] + bv0, acc[mb][nb][1] + bv0);
            float2 v1 = make_float2(acc[mb][nb][2] + bv1, acc[mb][nb][3] + bv1);
            *reinterpret_cast<float2*>(o0 + nb * 8) = v0;
            *reinterpret_cast<float2*>(o1 + nb * 8) = v1;
        }
    }
}

// ---------------------------------------------------------------------------
// Kernel 3: causal windowed mean (L = min(4g+1,16)) broadcast to 4 outputs.
// One block per (b,c) row, staged through SMEM.
// ---------------------------------------------------------------------------
__global__ void window_kernel(const float* __restrict__ ff2, float* __restrict__ ret)
{
    __shared__ float s[T_];
    const size_t row = blockIdx.x;
    const float4* p4 = reinterpret_cast<const float4*>(ff2 + row * T_);
    float4* s4 = reinterpret_cast<float4*>(s);
    for (int i = threadIdx.x; i < T_ / 4; i += 256) s4[i] = p4[i];
    __syncthreads();
    float4* r4 = reinterpret_cast<float4*>(ret + row * T_);
    for (int g = threadIdx.x; g < T_ / 4; g += 256) {
        const int e = g * 4;
        const int L = (e + 1 < 16) ? (e + 1) : 16;
        float sum = 0.0f;
        #pragma unroll 4
        for (int j = e - L + 1; j <= e; j++) sum += s[j];
        const float avg = sum / (float)L;
        r4[g] = make_float4(avg, avg, avg, avg);
    }
}

// ---------------------------------------------------------------------------
// Launcher
// ---------------------------------------------------------------------------
extern "C" void kernel_launch(void* const* d_in, const int* in_sizes, int n_in,
                              void* d_out, int out_size)
{
    const float* x  = (const float*)d_in[0];
    const float* W1 = (const float*)d_in[1];
    const float* b1 = (const float*)d_in[2];
    const float* W2 = (const float*)d_in[3];
    const float* b2 = (const float*)d_in[4];

    float* out = (float*)d_out;
    float* ret = out;
    float* tap = out + NELEM;
    float* ff1 = out + 2 * NELEM;
    float* ff2 = out + 3 * NELEM;

    cudaFuncSetAttribute(gemm_mma_kernel,
                         cudaFuncAttributeMaxDynamicSharedMemorySize, GEMM_SMEM);

    // 1. pool -> tap
    pool_kernel<<<(int)(NELEM / 256), 256>>>(x, tap);

    // 2. ff1 = W1 @ tap + b1
    {
        dim3 grid(T_ / 128, C_ / 128, B_);
        gemm_mma_kernel<<<grid, 256, GEMM_SMEM>>>(W1, tap, b1, ff1);
    }

    // 3. ff2 = W2 @ ff1 + b2
    {
        dim3 grid(T_ / 128, C_ / 128, B_);
        gemm_mma_kernel<<<grid, 256, GEMM_SMEM>>>(W2, ff1, b2, ff2);
    }

    // 4. windowed mean + stride-4 broadcast -> ret
    window_kernel<<<B_ * C_, 256>>>(ff2, ret);
}

// round 4
// speedup vs baseline: 3.2630x; 1.2640x over previous
#include <cuda_runtime.h>
#include <cuda_fp16.h>
#include <cstdint>

// ---------------------------------------------------------------------------
// Problem constants
// ---------------------------------------------------------------------------
constexpr int B_ = 8;
constexpr int C_ = 1024;     // M and K of both GEMMs
constexpr int T_ = 2048;     // N of both GEMMs
constexpr long NELEM = (long)B_ * C_ * T_;   // 16,777,216

// d_out layout: [ret | tap | ff1 | ff2], each NELEM floats.

// ---------------------------------------------------------------------------
// Scratch (device globals)
// ---------------------------------------------------------------------------
__device__ __half g_xa[(size_t)B_ * C_ * T_];   // fp16(tap)  : B of GEMM1
__device__ __half g_xb[(size_t)B_ * C_ * T_];   // fp16(ff1)  : B of GEMM2
__device__ __half g_w1h[(size_t)C_ * C_];
__device__ __half g_w1l[(size_t)C_ * C_];
__device__ __half g_w2h[(size_t)C_ * C_];
__device__ __half g_w2l[(size_t)C_ * C_];

// ---------------------------------------------------------------------------
// helpers
// ---------------------------------------------------------------------------
__device__ __forceinline__ uint32_t smem_u32(const void* p) {
    uint32_t a;
    asm("{ .reg .u64 t; cvta.to.shared.u64 t, %1; cvt.u32.u64 %0, t; }"
        : "=r"(a) : "l"(p));
    return a;
}
__device__ __forceinline__ void cp_async16(uint32_t sdst, const void* gsrc) {
    asm volatile("cp.async.cg.shared.global [%0], [%1], 16;" :: "r"(sdst), "l"(gsrc));
}
__device__ __forceinline__ void cp_commit() {
    asm volatile("cp.async.commit_group;" ::: "memory");
}
template <int N>
__device__ __forceinline__ void cp_wait() {
    asm volatile("cp.async.wait_group %0;" :: "n"(N) : "memory");
}
__device__ __forceinline__ void ldsm_x4(uint32_t (&r)[4], uint32_t addr) {
    asm volatile("ldmatrix.sync.aligned.m8n8.x4.shared.b16 {%0,%1,%2,%3}, [%4];"
        : "=r"(r[0]), "=r"(r[1]), "=r"(r[2]), "=r"(r[3]) : "r"(addr));
}
__device__ __forceinline__ void ldsm_x2t(uint32_t (&r)[2], uint32_t addr) {
    asm volatile("ldmatrix.sync.aligned.m8n8.x2.trans.shared.b16 {%0,%1}, [%2];"
        : "=r"(r[0]), "=r"(r[1]) : "r"(addr));
}
__device__ __forceinline__ void mma_f16(float (&d)[4],
                                        const uint32_t (&a)[4],
                                        const uint32_t (&b)[2]) {
    asm volatile(
        "mma.sync.aligned.m16n8k16.row.col.f32.f16.f16.f32 "
        "{%0,%1,%2,%3}, {%4,%5,%6,%7}, {%8,%9}, {%0,%1,%2,%3};"
        : "+f"(d[0]), "+f"(d[1]), "+f"(d[2]), "+f"(d[3])
        : "r"(a[0]), "r"(a[1]), "r"(a[2]), "r"(a[3]), "r"(b[0]), "r"(b[1]));
}

// ---------------------------------------------------------------------------
// Kernel: W -> fp16 hi/lo split
// ---------------------------------------------------------------------------
__global__ void wconv_kernel(const float* __restrict__ W,
                             __half* __restrict__ wh, __half* __restrict__ wl)
{
    int i = blockIdx.x * 256 + threadIdx.x;
    float v = W[i];
    __half h = __float2half(v);
    wh[i] = h;
    wl[i] = __float2half(v - __half2float(h));
}

// ---------------------------------------------------------------------------
// Kernel: 4:1 mean pool -> tap (fp32) + fp16 copy into g_xa
// ---------------------------------------------------------------------------
__global__ void pool_kernel(const float* __restrict__ x, float* __restrict__ tap)
{
    long i = (long)blockIdx.x * blockDim.x + threadIdx.x;
    if (i >= NELEM) return;
    float4 v = reinterpret_cast<const float4*>(x)[i];
    float m = 0.25f * (v.x + v.y + v.z + v.w);
    tap[i] = m;
    g_xa[i] = __float2half(m);
}

// ---------------------------------------------------------------------------
// GEMM (fp16 2-term HMMA):
//   out[b][m][n] = sum_k (Wh+Wl)[m][k] * Xh[b][k][n] + bias[m]
// CTA tile 128(M) x 256(N), KC=32, 3-stage cp.async pipeline, 256 threads,
// warp tile 64x64 (2x4 warps). Optional fused fp16 write of the output.
// ---------------------------------------------------------------------------
constexpr int KC = 32;
constexpr int A_STR = 80;                 // bytes per A row (64 + 16 pad)
constexpr int B_STR = 528;                // bytes per B row (512 + 16 pad)
constexpr int OF_AH = 0;
constexpr int OF_AL = 128 * A_STR;        // 10240
constexpr int OF_BH = 2 * 128 * A_STR;    // 20480
constexpr int STAGE_BYTES = OF_BH + KC * B_STR;   // 37376
constexpr int STAGES = 3;
constexpr int GEMM_SMEM = STAGES * STAGE_BYTES;   // 112128
constexpr int NCHUNK = C_ / KC;                   // 32

__global__ __launch_bounds__(256, 1)
void gemm_kernel(const __half* __restrict__ Wh,
                 const __half* __restrict__ Wl,
                 const __half* __restrict__ Xh,     // [B][C][T]
                 const float*  __restrict__ bias,
                 float* __restrict__ out,           // [B][C][T]
                 __half* __restrict__ out_h)        // nullable fp16 mirror
{
    extern __shared__ __align__(128) char smem[];
    const uint32_t sb = smem_u32(smem);

    const int tid  = threadIdx.x;
    const int wid  = tid >> 5;
    const int lane = tid & 31;
    const int bn = blockIdx.x * 256;
    const int bm = blockIdx.y * 128;
    const int bz = blockIdx.z;

    const int wm = (wid & 1) * 64;
    const int wn = (wid >> 1) * 64;

    const __half* Xb = Xh + (size_t)bz * C_ * T_;

    // cp.async task mappings
    const int a_r = tid >> 2;            // 0..63 base (2 iters -> 128 rows)
    const int a_c = tid & 3;             // 16B chunk in row
    const int b_k = tid >> 5;            // 0..7 base (4 iters -> 32 rows)
    const int b_c = tid & 31;            // 16B chunk in row

    auto load_stage = [&](int ch, int stg) {
        const int k0 = ch * KC;
        const uint32_t st = sb + stg * STAGE_BYTES;
        #pragma unroll
        for (int i = 0; i < 2; i++) {
            int r = a_r + i * 64;
            uint32_t sd = st + OF_AH + r * A_STR + a_c * 16;
            const __half* g = Wh + (size_t)(bm + r) * C_ + k0 + a_c * 8;
            cp_async16(sd, g);
            const __half* g2 = Wl + (size_t)(bm + r) * C_ + k0 + a_c * 8;
            cp_async16(sd + (OF_AL - OF_AH), g2);
        }
        #pragma unroll
        for (int i = 0; i < 4; i++) {
            int kr = b_k + i * 8;
            uint32_t sd = st + OF_BH + kr * B_STR + b_c * 16;
            const __half* g = Xb + (size_t)(k0 + kr) * T_ + bn + b_c * 8;
            cp_async16(sd, g);
        }
        cp_commit();
    };

    float acc[4][8][4];
    #pragma unroll
    for (int i = 0; i < 4; i++)
        #pragma unroll
        for (int j = 0; j < 8; j++)
            #pragma unroll
            for (int k = 0; k < 4; k++)
                acc[i][j][k] = 0.0f;

    // prologue: fill STAGES-1 stages
    load_stage(0, 0);
    load_stage(1, 1);

    const int lA_row = lane & 15;
    const int lA_kb  = (lane >> 4) * 16;    // byte offset within k16 block
    const int lB_row = lane & 15;

    for (int ch = 0; ch < NCHUNK; ch++) {
        cp_wait<STAGES - 2>();
        __syncthreads();

        // issue loads for ch+2 into the stage freed at ch-1
        if (ch + STAGES - 1 < NCHUNK)
            load_stage(ch + STAGES - 1, (ch + STAGES - 1) % STAGES);
        else
            cp_commit();   // keep group counts consistent

        const uint32_t st = sb + (ch % STAGES) * STAGE_BYTES;

        #pragma unroll
        for (int ks = 0; ks < 2; ks++) {
            uint32_t ah[4][4], al[4][4];
            #pragma unroll
            for (int mb = 0; mb < 4; mb++) {
                uint32_t off = (uint32_t)((wm + mb * 16 + lA_row) * A_STR
                                          + ks * 32 + lA_kb);
                ldsm_x4(ah[mb], st + OF_AH + off);
                ldsm_x4(al[mb], st + OF_AL + off);
            }
            #pragma unroll
            for (int nb = 0; nb < 8; nb++) {
                uint32_t b[2];
                uint32_t off = (uint32_t)((ks * 16 + lB_row) * B_STR
                                          + (wn + nb * 8) * 2);
                ldsm_x2t(b, st + OF_BH + off);
                #pragma unroll
                for (int mb = 0; mb < 4; mb++) {
                    mma_f16(acc[mb][nb], ah[mb], b);
                    mma_f16(acc[mb][nb], al[mb], b);
                }
            }
        }
        __syncthreads();
    }

    // epilogue: bias + fp32 store (+ optional fp16 mirror)
    const int r_lo = lane >> 2;
    const int c_lo = (lane & 3) * 2;
    #pragma unroll
    for (int mb = 0; mb < 4; mb++) {
        int gr0 = bm + wm + mb * 16 + r_lo;
        int gr1 = gr0 + 8;
        float bv0 = bias[gr0];
        float bv1 = bias[gr1];
        size_t ro0 = ((size_t)bz * C_ + gr0) * T_ + bn + wn + c_lo;
        size_t ro1 = ((size_t)bz * C_ + gr1) * T_ + bn + wn + c_lo;
        #pragma unroll
        for (int nb = 0; nb < 8; nb++) {
            float v00 = acc[mb][nb][0] + bv0, v01 = acc[mb][nb][1] + bv0;
            float v10 = acc[mb][nb][2] + bv1, v11 = acc[mb][nb][3] + bv1;
            *reinterpret_cast<float2*>(out + ro0 + nb * 8) = make_float2(v00, v01);
            *reinterpret_cast<float2*>(out + ro1 + nb * 8) = make_float2(v10, v11);
            if (out_h) {
                __half2 h0; h0.x = __float2half(v00); h0.y = __float2half(v01);
                __half2 h1; h1.x = __float2half(v10); h1.y = __float2half(v11);
                *reinterpret_cast<__half2*>(out_h + ro0 + nb * 8) = h0;
                *reinterpret_cast<__half2*>(out_h + ro1 + nb * 8) = h1;
            }
        }
    }
}

// ---------------------------------------------------------------------------
// Kernel: causal windowed mean (L = min(4g+1,16)) broadcast to 4 outputs.
// ---------------------------------------------------------------------------
__global__ void window_kernel(const float* __restrict__ ff2, float* __restrict__ ret)
{
    __shared__ float s[T_];
    const size_t row = blockIdx.x;
    const float4* p4 = reinterpret_cast<const float4*>(ff2 + row * T_);
    float4* s4 = reinterpret_cast<float4*>(s);
    for (int i = threadIdx.x; i < T_ / 4; i += 256) s4[i] = p4[i];
    __syncthreads();
    float4* r4 = reinterpret_cast<float4*>(ret + row * T_);
    for (int g = threadIdx.x; g < T_ / 4; g += 256) {
        const int e = g * 4;
        const int L = (e + 1 < 16) ? (e + 1) : 16;
        float sum = 0.0f;
        #pragma unroll 4
        for (int j = e - L + 1; j <= e; j++) sum += s[j];
        const float avg = sum / (float)L;
        r4[g] = make_float4(avg, avg, avg, avg);
    }
}

// ---------------------------------------------------------------------------
// Launcher
// ---------------------------------------------------------------------------
extern "C" void kernel_launch(void* const* d_in, const int* in_sizes, int n_in,
                              void* d_out, int out_size)
{
    const float* x  = (const float*)d_in[0];
    const float* W1 = (const float*)d_in[1];
    const float* b1 = (const float*)d_in[2];
    const float* W2 = (const float*)d_in[3];
    const float* b2 = (const float*)d_in[4];

    float* out = (float*)d_out;
    float* ret = out;
    float* tap = out + NELEM;
    float* ff1 = out + 2 * NELEM;
    float* ff2 = out + 3 * NELEM;

    cudaFuncSetAttribute(gemm_kernel,
                         cudaFuncAttributeMaxDynamicSharedMemorySize, GEMM_SMEM);

    // resolve device-global scratch addresses (graph-capturable: host-side only)
    static __half *xa = nullptr, *xb = nullptr, *w1h, *w1l, *w2h, *w2l;
    if (!xa) {
        cudaGetSymbolAddress((void**)&xa,  g_xa);
        cudaGetSymbolAddress((void**)&xb,  g_xb);
        cudaGetSymbolAddress((void**)&w1h, g_w1h);
        cudaGetSymbolAddress((void**)&w1l, g_w1l);
        cudaGetSymbolAddress((void**)&w2h, g_w2h);
        cudaGetSymbolAddress((void**)&w2l, g_w2l);
    }

    // 1. W splits
    wconv_kernel<<<(C_ * C_) / 256, 256>>>(W1, w1h, w1l);
    wconv_kernel<<<(C_ * C_) / 256, 256>>>(W2, w2h, w2l);

    // 2. pool -> tap fp32 + g_xa fp16
    pool_kernel<<<(int)(NELEM / 256), 256>>>(x, tap);

    // 3. ff1 = W1 @ tap + b1   (writes ff1 fp32 + g_xb fp16)
    {
        dim3 grid(T_ / 256, C_ / 128, B_);
        gemm_kernel<<<grid, 256, GEMM_SMEM>>>(w1h, w1l, xa, b1, ff1, xb);
    }

    // 4. ff2 = W2 @ ff1 + b2
    {
        dim3 grid(T_ / 256, C_ / 128, B_);
        gemm_kernel<<<grid, 256, GEMM_SMEM>>>(w2h, w2l, xb, b2, ff2, nullptr);
    }

    // 5. windowed mean + stride-4 broadcast -> ret
    window_kernel<<<B_ * C_, 256>>>(ff2, ret);
}

// round 5
// speedup vs baseline: 3.3591x; 1.0295x over previous
#include <cuda_runtime.h>
#include <cuda_fp16.h>
#include <cstdint>

// ---------------------------------------------------------------------------
// Problem constants
// ---------------------------------------------------------------------------
constexpr int B_ = 8;
constexpr int C_ = 1024;     // M and K of both GEMMs
constexpr int T_ = 2048;     // N of both GEMMs
constexpr long NELEM = (long)B_ * C_ * T_;   // 16,777,216

// d_out layout: [ret | tap | ff1 | ff2], each NELEM floats.

// ---------------------------------------------------------------------------
// Scratch (device globals)
// ---------------------------------------------------------------------------
__device__ __half g_xa[(size_t)B_ * C_ * T_];   // fp16(tap)  : B of GEMM1
__device__ __half g_xb[(size_t)B_ * C_ * T_];   // fp16(ff1)  : B of GEMM2
__device__ __half g_w1h[(size_t)C_ * C_];
__device__ __half g_w1l[(size_t)C_ * C_];
__device__ __half g_w2h[(size_t)C_ * C_];
__device__ __half g_w2l[(size_t)C_ * C_];

// ---------------------------------------------------------------------------
// helpers
// ---------------------------------------------------------------------------
__device__ __forceinline__ uint32_t smem_u32(const void* p) {
    uint32_t a;
    asm("{ .reg .u64 t; cvta.to.shared.u64 t, %1; cvt.u32.u64 %0, t; }"
        : "=r"(a) : "l"(p));
    return a;
}
__device__ __forceinline__ void cp_async16(uint32_t sdst, const void* gsrc) {
    asm volatile("cp.async.cg.shared.global [%0], [%1], 16;" :: "r"(sdst), "l"(gsrc));
}
__device__ __forceinline__ void cp_commit() {
    asm volatile("cp.async.commit_group;" ::: "memory");
}
template <int N>
__device__ __forceinline__ void cp_wait() {
    asm volatile("cp.async.wait_group %0;" :: "n"(N) : "memory");
}
__device__ __forceinline__ void ldsm_x4(uint32_t (&r)[4], uint32_t addr) {
    asm volatile("ldmatrix.sync.aligned.m8n8.x4.shared.b16 {%0,%1,%2,%3}, [%4];"
        : "=r"(r[0]), "=r"(r[1]), "=r"(r[2]), "=r"(r[3]) : "r"(addr));
}
__device__ __forceinline__ void ldsm_x2t(uint32_t (&r)[2], uint32_t addr) {
    asm volatile("ldmatrix.sync.aligned.m8n8.x2.trans.shared.b16 {%0,%1}, [%2];"
        : "=r"(r[0]), "=r"(r[1]) : "r"(addr));
}
__device__ __forceinline__ void mma_f16(float (&d)[4],
                                        const uint32_t (&a)[4],
                                        const uint32_t (&b)[2]) {
    asm volatile(
        "mma.sync.aligned.m16n8k16.row.col.f32.f16.f16.f32 "
        "{%0,%1,%2,%3}, {%4,%5,%6,%7}, {%8,%9}, {%0,%1,%2,%3};"
        : "+f"(d[0]), "+f"(d[1]), "+f"(d[2]), "+f"(d[3])
        : "r"(a[0]), "r"(a[1]), "r"(a[2]), "r"(a[3]), "r"(b[0]), "r"(b[1]));
}

// ---------------------------------------------------------------------------
// Kernel: W -> fp16 hi/lo split
// ---------------------------------------------------------------------------
__global__ void wconv_kernel(const float* __restrict__ W,
                             __half* __restrict__ wh, __half* __restrict__ wl)
{
    int i = blockIdx.x * 256 + threadIdx.x;
    float v = W[i];
    __half h = __float2half(v);
    wh[i] = h;
    wl[i] = __float2half(v - __half2float(h));
}

// ---------------------------------------------------------------------------
// Kernel: 4:1 mean pool -> tap (fp32) + fp16 copy into g_xa
// ---------------------------------------------------------------------------
__global__ void pool_kernel(const float* __restrict__ x, float* __restrict__ tap)
{
    long i = (long)blockIdx.x * blockDim.x + threadIdx.x;
    if (i >= NELEM) return;
    float4 v = reinterpret_cast<const float4*>(x)[i];
    float m = 0.25f * (v.x + v.y + v.z + v.w);
    tap[i] = m;
    g_xa[i] = __float2half(m);
}

// ---------------------------------------------------------------------------
// GEMM (fp16 2-term HMMA):
//   out[b][m][n] = sum_k (Wh+Wl)[m][k] * Xh[b][k][n] + bias[m]
// CTA tile 128(M) x 256(N), KC=32, 4-stage cp.async pipeline, 512 threads,
// 16 warps in 2(M) x 8(N) grid, warp tile 64x32. One barrier per chunk.
// ---------------------------------------------------------------------------
constexpr int KC = 32;
constexpr int A_STR = 80;                 // bytes per A row (64 + 16 pad)
constexpr int B_STR = 528;                // bytes per B row (512 + 16 pad)
constexpr int OF_AH = 0;
constexpr int OF_AL = 128 * A_STR;        // 10240
constexpr int OF_BH = 2 * 128 * A_STR;    // 20480
constexpr int STAGE_BYTES = OF_BH + KC * B_STR;   // 37376
constexpr int STAGES = 4;
constexpr int GEMM_SMEM = STAGES * STAGE_BYTES;   // 149504
constexpr int NCHUNK = C_ / KC;                   // 32

__global__ __launch_bounds__(512, 1)
void gemm_kernel(const __half* __restrict__ Wh,
                 const __half* __restrict__ Wl,
                 const __half* __restrict__ Xh,     // [B][C][T]
                 const float*  __restrict__ bias,
                 float* __restrict__ out,           // [B][C][T]
                 __half* __restrict__ out_h)        // nullable fp16 mirror
{
    extern __shared__ __align__(128) char smem[];
    const uint32_t sb = smem_u32(smem);

    const int tid  = threadIdx.x;
    const int wid  = tid >> 5;
    const int lane = tid & 31;
    const int bn = blockIdx.x * 256;
    const int bm = blockIdx.y * 128;
    const int bz = blockIdx.z;

    const int wm = (wid & 1) * 64;     // 2 warps over M
    const int wn = (wid >> 1) * 32;    // 8 warps over N

    const __half* Xb = Xh + (size_t)bz * C_ * T_;

    // cp.async task mappings (512 threads)
    const int a_r = tid >> 2;            // 0..127 : A row
    const int a_c = tid & 3;             // 16B chunk in A row (4 x 8 halves)
    const int b_k = tid >> 5;            // 0..15 : B row base (2 iters -> 32)
    const int b_c = tid & 31;            // 16B chunk in B row (32 x 8 halves)

    auto load_stage = [&](int ch, int stg) {
        const int k0 = ch * KC;
        const uint32_t st = sb + stg * STAGE_BYTES;
        {
            uint32_t sd = st + OF_AH + a_r * A_STR + a_c * 16;
            const __half* g  = Wh + (size_t)(bm + a_r) * C_ + k0 + a_c * 8;
            const __half* g2 = Wl + (size_t)(bm + a_r) * C_ + k0 + a_c * 8;
            cp_async16(sd, g);
            cp_async16(sd + (OF_AL - OF_AH), g2);
        }
        #pragma unroll
        for (int i = 0; i < 2; i++) {
            int kr = b_k + i * 16;
            uint32_t sd = st + OF_BH + kr * B_STR + b_c * 16;
            const __half* g = Xb + (size_t)(k0 + kr) * T_ + bn + b_c * 8;
            cp_async16(sd, g);
        }
        cp_commit();
    };

    float acc[4][4][4];
    #pragma unroll
    for (int i = 0; i < 4; i++)
        #pragma unroll
        for (int j = 0; j < 4; j++)
            #pragma unroll
            for (int k = 0; k < 4; k++)
                acc[i][j][k] = 0.0f;

    // prologue: fill STAGES-1 stages
    load_stage(0, 0);
    load_stage(1, 1);
    load_stage(2, 2);

    const int lA_row = lane & 15;
    const int lA_kb  = (lane >> 4) * 16;    // byte offset within k16 block
    const int lB_row = lane & 15;

    for (int ch = 0; ch < NCHUNK; ch++) {
        cp_wait<STAGES - 2>();
        __syncthreads();

        if (ch + STAGES - 1 < NCHUNK)
            load_stage(ch + STAGES - 1, (ch + STAGES - 1) % STAGES);
        else
            cp_commit();   // keep group counts consistent

        const uint32_t st = sb + (ch % STAGES) * STAGE_BYTES;

        #pragma unroll
        for (int ks = 0; ks < 2; ks++) {
            // B fragments for this warp's 32 columns
            uint32_t b[4][2];
            #pragma unroll
            for (int nb = 0; nb < 4; nb++) {
                uint32_t off = (uint32_t)((ks * 16 + lB_row) * B_STR
                                          + (wn + nb * 8) * 2);
                ldsm_x2t(b[nb], st + OF_BH + off);
            }
            // A fragments per 16-row block, consumed immediately
            #pragma unroll
            for (int mb = 0; mb < 4; mb++) {
                uint32_t ah[4], al[4];
                uint32_t off = (uint32_t)((wm + mb * 16 + lA_row) * A_STR
                                          + ks * 32 + lA_kb);
                ldsm_x4(ah, st + OF_AH + off);
                ldsm_x4(al, st + OF_AL + off);
                #pragma unroll
                for (int nb = 0; nb < 4; nb++) {
                    mma_f16(acc[mb][nb], ah, b[nb]);
                    mma_f16(acc[mb][nb], al, b[nb]);
                }
            }
        }
        // NOTE: no second barrier — the top-of-loop barrier at iteration ch+1
        // orders compute(ch) before any overwrite of stage ch%STAGES (which is
        // first re-targeted by load_stage(ch+STAGES) issued at iteration ch+1).
    }

    // epilogue: bias + fp32 store (+ optional fp16 mirror)
    const int r_lo = lane >> 2;
    const int c_lo = (lane & 3) * 2;
    #pragma unroll
    for (int mb = 0; mb < 4; mb++) {
        int gr0 = bm + wm + mb * 16 + r_lo;
        int gr1 = gr0 + 8;
        float bv0 = bias[gr0];
        float bv1 = bias[gr1];
        size_t ro0 = ((size_t)bz * C_ + gr0) * T_ + bn + wn + c_lo;
        size_t ro1 = ((size_t)bz * C_ + gr1) * T_ + bn + wn + c_lo;
        #pragma unroll
        for (int nb = 0; nb < 4; nb++) {
            float v00 = acc[mb][nb][0] + bv0, v01 = acc[mb][nb][1] + bv0;
            float v10 = acc[mb][nb][2] + bv1, v11 = acc[mb][nb][3] + bv1;
            *reinterpret_cast<float2*>(out + ro0 + nb * 8) = make_float2(v00, v01);
            *reinterpret_cast<float2*>(out + ro1 + nb * 8) = make_float2(v10, v11);
            if (out_h) {
                __half2 h0; h0.x = __float2half(v00); h0.y = __float2half(v01);
                __half2 h1; h1.x = __float2half(v10); h1.y = __float2half(v11);
                *reinterpret_cast<__half2*>(out_h + ro0 + nb * 8) = h0;
                *reinterpret_cast<__half2*>(out_h + ro1 + nb * 8) = h1;
            }
        }
    }
}

// ---------------------------------------------------------------------------
// Kernel: causal windowed mean (L = min(4g+1,16)) broadcast to 4 outputs.
// ---------------------------------------------------------------------------
__global__ void window_kernel(const float* __restrict__ ff2, float* __restrict__ ret)
{
    __shared__ float s[T_];
    const size_t row = blockIdx.x;
    const float4* p4 = reinterpret_cast<const float4*>(ff2 + row * T_);
    float4* s4 = reinterpret_cast<float4*>(s);
    for (int i = threadIdx.x; i < T_ / 4; i += 256) s4[i] = p4[i];
    __syncthreads();
    float4* r4 = reinterpret_cast<float4*>(ret + row * T_);
    for (int g = threadIdx.x; g < T_ / 4; g += 256) {
        const int e = g * 4;
        const int L = (e + 1 < 16) ? (e + 1) : 16;
        float sum = 0.0f;
        #pragma unroll 4
        for (int j = e - L + 1; j <= e; j++) sum += s[j];
        const float avg = sum / (float)L;
        r4[g] = make_float4(avg, avg, avg, avg);
    }
}

// ---------------------------------------------------------------------------
// Launcher
// ---------------------------------------------------------------------------
extern "C" void kernel_launch(void* const* d_in, const int* in_sizes, int n_in,
                              void* d_out, int out_size)
{
    const float* x  = (const float*)d_in[0];
    const float* W1 = (const float*)d_in[1];
    const float* b1 = (const float*)d_in[2];
    const float* W2 = (const float*)d_in[3];
    const float* b2 = (const float*)d_in[4];

    float* out = (float*)d_out;
    float* ret = out;
    float* tap = out + NELEM;
    float* ff1 = out + 2 * NELEM;
    float* ff2 = out + 3 * NELEM;

    cudaFuncSetAttribute(gemm_kernel,
                         cudaFuncAttributeMaxDynamicSharedMemorySize, GEMM_SMEM);

    static __half *xa = nullptr, *xb = nullptr, *w1h, *w1l, *w2h, *w2l;
    if (!xa) {
        cudaGetSymbolAddress((void**)&xa,  g_xa);
        cudaGetSymbolAddress((void**)&xb,  g_xb);
        cudaGetSymbolAddress((void**)&w1h, g_w1h);
        cudaGetSymbolAddress((void**)&w1l, g_w1l);
        cudaGetSymbolAddress((void**)&w2h, g_w2h);
        cudaGetSymbolAddress((void**)&w2l, g_w2l);
    }

    // 1. W splits
    wconv_kernel<<<(C_ * C_) / 256, 256>>>(W1, w1h, w1l);
    wconv_kernel<<<(C_ * C_) / 256, 256>>>(W2, w2h, w2l);

    // 2. pool -> tap fp32 + g_xa fp16
    pool_kernel<<<(int)(NELEM / 256), 256>>>(x, tap);

    // 3. ff1 = W1 @ tap + b1   (writes ff1 fp32 + g_xb fp16)
    {
        dim3 grid(T_ / 256, C_ / 128, B_);
        gemm_kernel<<<grid, 512, GEMM_SMEM>>>(w1h, w1l, xa, b1, ff1, xb);
    }

    // 4. ff2 = W2 @ ff1 + b2
    {
        dim3 grid(T_ / 256, C_ / 128, B_);
        gemm_kernel<<<grid, 512, GEMM_SMEM>>>(w2h, w2l, xb, b2, ff2, nullptr);
    }

    // 5. windowed mean + stride-4 broadcast -> ret
    window_kernel<<<B_ * C_, 256>>>(ff2, ret);
}

// round 6
// speedup vs baseline: 3.3911x; 1.0095x over previous
#include <cuda_runtime.h>
#include <cuda_fp16.h>
#include <cstdint>

// ---------------------------------------------------------------------------
// Problem constants
// ---------------------------------------------------------------------------
constexpr int B_ = 8;
constexpr int C_ = 1024;     // M and K of both GEMMs
constexpr int T_ = 2048;     // N of both GEMMs
constexpr long NELEM = (long)B_ * C_ * T_;   // 16,777,216

// d_out layout: [ret | tap | ff1 | ff2], each NELEM floats.

// ---------------------------------------------------------------------------
// Scratch (device globals)
// ---------------------------------------------------------------------------
__device__ __half g_xa[(size_t)B_ * C_ * T_];   // fp16(tap)  : B of GEMM1
__device__ __half g_xb[(size_t)B_ * C_ * T_];   // fp16(ff1)  : B of GEMM2
__device__ __half g_w1h[(size_t)C_ * C_];
__device__ __half g_w1l[(size_t)C_ * C_];
__device__ __half g_w2h[(size_t)C_ * C_];
__device__ __half g_w2l[(size_t)C_ * C_];

// ---------------------------------------------------------------------------
// helpers
// ---------------------------------------------------------------------------
__device__ __forceinline__ uint32_t smem_u32(const void* p) {
    uint32_t a;
    asm("{ .reg .u64 t; cvta.to.shared.u64 t, %1; cvt.u32.u64 %0, t; }"
        : "=r"(a) : "l"(p));
    return a;
}
__device__ __forceinline__ void cp_async16(uint32_t sdst, const void* gsrc) {
    asm volatile("cp.async.cg.shared.global [%0], [%1], 16;" :: "r"(sdst), "l"(gsrc));
}
__device__ __forceinline__ void cp_commit() {
    asm volatile("cp.async.commit_group;" ::: "memory");
}
template <int N>
__device__ __forceinline__ void cp_wait() {
    asm volatile("cp.async.wait_group %0;" :: "n"(N) : "memory");
}
__device__ __forceinline__ void ldsm_x4(uint32_t (&r)[4], uint32_t addr) {
    asm volatile("ldmatrix.sync.aligned.m8n8.x4.shared.b16 {%0,%1,%2,%3}, [%4];"
        : "=r"(r[0]), "=r"(r[1]), "=r"(r[2]), "=r"(r[3]) : "r"(addr));
}
__device__ __forceinline__ void ldsm_x4t(uint32_t (&r)[4], uint32_t addr) {
    asm volatile("ldmatrix.sync.aligned.m8n8.x4.trans.shared.b16 {%0,%1,%2,%3}, [%4];"
        : "=r"(r[0]), "=r"(r[1]), "=r"(r[2]), "=r"(r[3]) : "r"(addr));
}
__device__ __forceinline__ void mma_f16(float (&d)[4],
                                        const uint32_t (&a)[4],
                                        const uint32_t* b) {
    asm volatile(
        "mma.sync.aligned.m16n8k16.row.col.f32.f16.f16.f32 "
        "{%0,%1,%2,%3}, {%4,%5,%6,%7}, {%8,%9}, {%0,%1,%2,%3};"
        : "+f"(d[0]), "+f"(d[1]), "+f"(d[2]), "+f"(d[3])
        : "r"(a[0]), "r"(a[1]), "r"(a[2]), "r"(a[3]), "r"(b[0]), "r"(b[1]));
}

// ---------------------------------------------------------------------------
// Kernel: W -> fp16 hi/lo split
// ---------------------------------------------------------------------------
__global__ void wconv_kernel(const float* __restrict__ W,
                             __half* __restrict__ wh, __half* __restrict__ wl)
{
    int i = blockIdx.x * 256 + threadIdx.x;
    float v = W[i];
    __half h = __float2half(v);
    wh[i] = h;
    wl[i] = __float2half(v - __half2float(h));
}

// ---------------------------------------------------------------------------
// Kernel: 4:1 mean pool -> tap (fp32) + fp16 copy into g_xa
// ---------------------------------------------------------------------------
__global__ void pool_kernel(const float* __restrict__ x, float* __restrict__ tap)
{
    long i = (long)blockIdx.x * blockDim.x + threadIdx.x;
    if (i >= NELEM) return;
    float4 v = reinterpret_cast<const float4*>(x)[i];
    float m = 0.25f * (v.x + v.y + v.z + v.w);
    tap[i] = m;
    g_xa[i] = __float2half(m);
}

// ---------------------------------------------------------------------------
// GEMM (fp16 2-term HMMA):
//   out[b][m][n] = sum_k (Wh+Wl)[m][k] * Xh[b][k][n] + bias[m]
// CTA tile 128(M) x 256(N), KC=32, 5-stage cp.async pipeline, 512 threads,
// 16 warps in 4(M) x 4(N) grid, warp tile 32x64. One barrier per chunk.
// ---------------------------------------------------------------------------
constexpr int KC = 32;
constexpr int A_STR = 80;                 // bytes per A row (64 + 16 pad)
constexpr int B_STR = 528;                // bytes per B row (512 + 16 pad)
constexpr int OF_AH = 0;
constexpr int OF_AL = 128 * A_STR;        // 10240
constexpr int OF_BH = 2 * 128 * A_STR;    // 20480
constexpr int STAGE_BYTES = OF_BH + KC * B_STR;   // 37376
constexpr int STAGES = 5;
constexpr int GEMM_SMEM = STAGES * STAGE_BYTES;   // 186880
constexpr int NCHUNK = C_ / KC;                   // 32

__global__ __launch_bounds__(512, 1)
void gemm_kernel(const __half* __restrict__ Wh,
                 const __half* __restrict__ Wl,
                 const __half* __restrict__ Xh,     // [B][C][T]
                 const float*  __restrict__ bias,
                 float* __restrict__ out,           // [B][C][T]
                 __half* __restrict__ out_h)        // nullable fp16 mirror
{
    extern __shared__ __align__(128) char smem[];
    const uint32_t sb = smem_u32(smem);

    const int tid  = threadIdx.x;
    const int wid  = tid >> 5;
    const int lane = tid & 31;
    const int bn = blockIdx.x * 256;
    const int bm = blockIdx.y * 128;
    const int bz = blockIdx.z;

    const int wm = (wid & 3) * 32;     // 4 warps over M
    const int wn = (wid >> 2) * 64;    // 4 warps over N

    const __half* Xb = Xh + (size_t)bz * C_ * T_;

    // cp.async task mappings (512 threads)
    const int a_r = tid >> 2;            // 0..127 : A row
    const int a_c = tid & 3;             // 16B chunk in A row
    const int b_k = tid >> 5;            // 0..15 : B row base (2 iters -> 32)
    const int b_c = tid & 31;            // 16B chunk in B row

    auto load_stage = [&](int ch, int stg) {
        const int k0 = ch * KC;
        const uint32_t st = sb + stg * STAGE_BYTES;
        {
            uint32_t sd = st + OF_AH + a_r * A_STR + a_c * 16;
            const __half* g  = Wh + (size_t)(bm + a_r) * C_ + k0 + a_c * 8;
            const __half* g2 = Wl + (size_t)(bm + a_r) * C_ + k0 + a_c * 8;
            cp_async16(sd, g);
            cp_async16(sd + (OF_AL - OF_AH), g2);
        }
        #pragma unroll
        for (int i = 0; i < 2; i++) {
            int kr = b_k + i * 16;
            uint32_t sd = st + OF_BH + kr * B_STR + b_c * 16;
            const __half* g = Xb + (size_t)(k0 + kr) * T_ + bn + b_c * 8;
            cp_async16(sd, g);
        }
        cp_commit();
    };

    float acc[2][8][4];
    #pragma unroll
    for (int i = 0; i < 2; i++)
        #pragma unroll
        for (int j = 0; j < 8; j++)
            #pragma unroll
            for (int k = 0; k < 4; k++)
                acc[i][j][k] = 0.0f;

    // prologue: fill STAGES-1 stages
    load_stage(0, 0);
    load_stage(1, 1);
    load_stage(2, 2);
    load_stage(3, 3);

    const int lA_row = lane & 15;
    const int lA_kb  = (lane >> 4) * 16;    // byte offset within k16 block
    const int lB_row = lane & 15;
    const int lB_nc  = (lane >> 4) * 8;     // n-column sub-block for x4t

    for (int ch = 0; ch < NCHUNK; ch++) {
        cp_wait<STAGES - 2>();
        __syncthreads();

        if (ch + STAGES - 1 < NCHUNK)
            load_stage(ch + STAGES - 1, (ch + STAGES - 1) % STAGES);
        else
            cp_commit();   // keep group counts consistent

        const uint32_t st = sb + (ch % STAGES) * STAGE_BYTES;

        #pragma unroll
        for (int ks = 0; ks < 2; ks++) {
            // B fragments: warp covers 64 cols = 4 ldsm_x4t (16 cols each)
            uint32_t b[8][2];
            #pragma unroll
            for (int nq = 0; nq < 4; nq++) {
                uint32_t r[4];
                uint32_t off = (uint32_t)((ks * 16 + lB_row) * B_STR
                                          + (wn + nq * 16 + lB_nc) * 2);
                ldsm_x4t(r, st + OF_BH + off);
                b[nq * 2 + 0][0] = r[0]; b[nq * 2 + 0][1] = r[1];
                b[nq * 2 + 1][0] = r[2]; b[nq * 2 + 1][1] = r[3];
            }
            // A fragments per 16-row block (hi+lo), consumed immediately
            #pragma unroll
            for (int mb = 0; mb < 2; mb++) {
                uint32_t ah[4], al[4];
                uint32_t off = (uint32_t)((wm + mb * 16 + lA_row) * A_STR
                                          + ks * 32 + lA_kb);
                ldsm_x4(ah, st + OF_AH + off);
                ldsm_x4(al, st + OF_AL + off);
                #pragma unroll
                for (int nb = 0; nb < 8; nb++) {
                    mma_f16(acc[mb][nb], ah, b[nb]);
                    mma_f16(acc[mb][nb], al, b[nb]);
                }
            }
        }
        // single barrier per chunk (top of loop) is sufficient: stage ch%STAGES
        // is only re-targeted by load_stage(ch+STAGES) issued at iteration ch+1,
        // which is after the next barrier.
    }

    // epilogue: bias + fp32 store (+ optional fp16 mirror)
    const int r_lo = lane >> 2;
    const int c_lo = (lane & 3) * 2;
    #pragma unroll
    for (int mb = 0; mb < 2; mb++) {
        int gr0 = bm + wm + mb * 16 + r_lo;
        int gr1 = gr0 + 8;
        float bv0 = bias[gr0];
        float bv1 = bias[gr1];
        size_t ro0 = ((size_t)bz * C_ + gr0) * T_ + bn + wn + c_lo;
        size_t ro1 = ((size_t)bz * C_ + gr1) * T_ + bn + wn + c_lo;
        #pragma unroll
        for (int nb = 0; nb < 8; nb++) {
            float v00 = acc[mb][nb][0] + bv0, v01 = acc[mb][nb][1] + bv0;
            float v10 = acc[mb][nb][2] + bv1, v11 = acc[mb][nb][3] + bv1;
            *reinterpret_cast<float2*>(out + ro0 + nb * 8) = make_float2(v00, v01);
            *reinterpret_cast<float2*>(out + ro1 + nb * 8) = make_float2(v10, v11);
            if (out_h) {
                __half2 h0; h0.x = __float2half(v00); h0.y = __float2half(v01);
                __half2 h1; h1.x = __float2half(v10); h1.y = __float2half(v11);
                *reinterpret_cast<__half2*>(out_h + ro0 + nb * 8) = h0;
                *reinterpret_cast<__half2*>(out_h + ro1 + nb * 8) = h1;
            }
        }
    }
}

// ---------------------------------------------------------------------------
// Kernel: causal windowed mean, via per-group partial sums.
//   pre[g] = sum of ff2[4g .. 4g+3]
//   g < 4 : sum = pre[0..g-1] + s[4g]           (L = 4g+1)
//   g >= 4: sum = s[4g] - s[4g-16] + pre[g-4..g-1]  (L = 16)
// ---------------------------------------------------------------------------
__global__ void window_kernel(const float* __restrict__ ff2, float* __restrict__ ret)
{
    __shared__ float s[T_];
    __shared__ float pre[T_ / 4];
    const size_t row = blockIdx.x;
    const float4* p4 = reinterpret_cast<const float4*>(ff2 + row * T_);
    float4* s4 = reinterpret_cast<float4*>(s);
    #pragma unroll
    for (int i = 0; i < 2; i++) {
        int idx = threadIdx.x + i * 256;
        float4 v = p4[idx];
        s4[idx] = v;
        pre[idx] = v.x + v.y + v.z + v.w;
    }
    __syncthreads();
    float4* r4 = reinterpret_cast<float4*>(ret + row * T_);
    #pragma unroll
    for (int i = 0; i < 2; i++) {
        int g = threadIdx.x + i * 256;
        float avg;
        if (g >= 4) {
            float sum = s[4 * g] - s[4 * g - 16]
                      + pre[g - 4] + pre[g - 3] + pre[g - 2] + pre[g - 1];
            avg = sum * 0.0625f;
        } else {
            float sum = s[4 * g];
            for (int q = 0; q < g; q++) sum += pre[q];
            avg = sum / (float)(4 * g + 1);
        }
        r4[g] = make_float4(avg, avg, avg, avg);
    }
}

// ---------------------------------------------------------------------------
// Launcher
// ---------------------------------------------------------------------------
extern "C" void kernel_launch(void* const* d_in, const int* in_sizes, int n_in,
                              void* d_out, int out_size)
{
    const float* x  = (const float*)d_in[0];
    const float* W1 = (const float*)d_in[1];
    const float* b1 = (const float*)d_in[2];
    const float* W2 = (const float*)d_in[3];
    const float* b2 = (const float*)d_in[4];

    float* out = (float*)d_out;
    float* ret = out;
    float* tap = out + NELEM;
    float* ff1 = out + 2 * NELEM;
    float* ff2 = out + 3 * NELEM;

    cudaFuncSetAttribute(gemm_kernel,
                         cudaFuncAttributeMaxDynamicSharedMemorySize, GEMM_SMEM);

    static __half *xa = nullptr, *xb = nullptr, *w1h, *w1l, *w2h, *w2l;
    if (!xa) {
        cudaGetSymbolAddress((void**)&xa,  g_xa);
        cudaGetSymbolAddress((void**)&xb,  g_xb);
        cudaGetSymbolAddress((void**)&w1h, g_w1h);
        cudaGetSymbolAddress((void**)&w1l, g_w1l);
        cudaGetSymbolAddress((void**)&w2h, g_w2h);
        cudaGetSymbolAddress((void**)&w2l, g_w2l);
    }

    // 1. W splits
    wconv_kernel<<<(C_ * C_) / 256, 256>>>(W1, w1h, w1l);
    wconv_kernel<<<(C_ * C_) / 256, 256>>>(W2, w2h, w2l);

    // 2. pool -> tap fp32 + g_xa fp16
    pool_kernel<<<(int)(NELEM / 256), 256>>>(x, tap);

    // 3. ff1 = W1 @ tap + b1   (writes ff1 fp32 + g_xb fp16)
    {
        dim3 grid(T_ / 256, C_ / 128, B_);
        gemm_kernel<<<grid, 512, GEMM_SMEM>>>(w1h, w1l, xa, b1, ff1, xb);
    }

    // 4. ff2 = W2 @ ff1 + b2
    {
        dim3 grid(T_ / 256, C_ / 128, B_);
        gemm_kernel<<<grid, 512, GEMM_SMEM>>>(w2h, w2l, xb, b2, ff2, nullptr);
    }

    // 5. windowed mean + stride-4 broadcast -> ret
    window_kernel<<<B_ * C_, 256>>>(ff2, ret);
}